// round 1
// baseline (speedup 1.0000x reference)
#include <cuda_runtime.h>
#include <cstdint>

#define HFD 112
#define WFD 112
#define P_SP 12544     // 112*112
#define CIN 32
#define CF 128
#define NB 16
#define NC 1000
#define EPSF 1e-6f

// ---- scratch (static device globals; no allocation) ----
__device__ float    g_A[(size_t)NB * CF * P_SP];   // conv activations
__device__ float    g_S[NB * CF];                  // spatial sums per channel
__device__ int      g_labels[NB * 2];
__device__ float    g_wgt[NB * 2 * CF];
__device__ float    g_cam[(size_t)NB * 2 * P_SP];
__device__ unsigned g_mm[NB * 2 * 2];              // [nk][0]=min bits, [1]=max bits (nonneg floats)

// ============================================================
// 1) 3x3 stride-2 SAME conv, fp32.
//    SAME padding for in=224, s=2, k=3: pad_lo=0, pad_hi=1.
//    Block: 64 threads, tile = 16x16 outputs x 8 filters.
//    Each thread: 4 consecutive x-outputs (shared 9-col input window),
//    1 row, 8 filters -> 32 accumulators. Weights staged in smem once.
// ============================================================
__global__ __launch_bounds__(64) void conv_kernel(const float* __restrict__ x,
                                                  const float* __restrict__ Wc,
                                                  const float* __restrict__ bc) {
    __shared__ __align__(16) float sIn[33 * 36];
    __shared__ __align__(16) float sW[8 * 32 * 12];
    const int tid = threadIdx.x;
    const int txT = blockIdx.x % 7, tyT = blockIdx.x / 7;
    const int cfg = blockIdx.y;     // 0..15, 8 filters each
    const int n   = blockIdx.z;

    // stage all weights for this block's 8 filters (all 32 cin)
    for (int i = tid; i < 8 * 32 * 9; i += 64) {
        int f = i / 288, rem = i % 288, c = rem / 9, j = rem % 9;
        sW[(f * 32 + c) * 12 + j] = Wc[(((cfg * 8 + f) * 32 + c) * 9) + j];
    }

    const int ihb = tyT * 32, iwb = txT * 32;
    const int ty = tid >> 2, txg = tid & 3;

    float acc[8][4];
#pragma unroll
    for (int f = 0; f < 8; ++f)
#pragma unroll
        for (int j = 0; j < 4; ++j) acc[f][j] = 0.f;

    const float* xb = x + (size_t)n * CIN * 224 * 224;
    for (int cin = 0; cin < CIN; ++cin) {
        __syncthreads();   // also covers weight staging on first iter
        const float* xc = xb + (size_t)cin * 224 * 224;
        for (int i = tid; i < 33 * 33; i += 64) {
            int r = i / 33, c = i % 33;
            int gr = ihb + r, gc = iwb + c;
            float v = (gr < 224 && gc < 224) ? xc[gr * 224 + gc] : 0.f;
            sIn[r * 36 + c] = v;
        }
        __syncthreads();
        const float* inb = &sIn[(2 * ty) * 36 + 8 * txg];
#pragma unroll
        for (int r = 0; r < 3; ++r) {
            const float4 v0 = *(const float4*)(inb + r * 36);
            const float4 v1 = *(const float4*)(inb + r * 36 + 4);
            const float  v8 = inb[r * 36 + 8];
            const float in0 = v0.x, in1 = v0.y, in2 = v0.z, in3 = v0.w;
            const float in4 = v1.x, in5 = v1.y, in6 = v1.z, in7 = v1.w;
#pragma unroll
            for (int f = 0; f < 8; ++f) {
                const float* wp = &sW[(f * 32 + cin) * 12 + 3 * r];
                const float w0 = wp[0], w1 = wp[1], w2 = wp[2];
                acc[f][0] += w0 * in0 + w1 * in1 + w2 * in2;
                acc[f][1] += w0 * in2 + w1 * in3 + w2 * in4;
                acc[f][2] += w0 * in4 + w1 * in5 + w2 * in6;
                acc[f][3] += w0 * in6 + w1 * in7 + w2 * v8;
            }
        }
    }
    const int oy = tyT * 16 + ty, oxb = txT * 16 + 4 * txg;
#pragma unroll
    for (int f = 0; f < 8; ++f) {
        const int cf = cfg * 8 + f;
        const float b = bc[cf];
        float4 o = make_float4(acc[f][0] + b, acc[f][1] + b, acc[f][2] + b, acc[f][3] + b);
        *(float4*)&g_A[((size_t)(n * CF + cf) * HFD + oy) * WFD + oxb] = o;
    }
}

// ============================================================
// 2) spatial sums S[n,cf] = sum_{h,w} A
// ============================================================
__global__ void gap_kernel() {
    const int b = blockIdx.x;                 // n*CF + cf, grid = 2048
    const float* p = g_A + (size_t)b * P_SP;
    float s = 0.f;
    for (int i = threadIdx.x; i < P_SP; i += 256) s += p[i];
#pragma unroll
    for (int o = 16; o; o >>= 1) s += __shfl_xor_sync(0xffffffffu, s, o);
    __shared__ float ss[8];
    if ((threadIdx.x & 31) == 0) ss[threadIdx.x >> 5] = s;
    __syncthreads();
    if (threadIdx.x == 0) {
        float t = 0.f;
#pragma unroll
        for (int i = 0; i < 8; ++i) t += ss[i];
        g_S[b] = t;
    }
}

// ============================================================
// 3) logits[n,c] = mean(A) . Wf[c,:] + bf[c]  -> written to d_out[0:16000]
// ============================================================
__global__ void logits_kernel(const float* __restrict__ Wf, const float* __restrict__ bf,
                              float* __restrict__ out) {
    const int idx = blockIdx.x * 256 + threadIdx.x;
    if (idx >= NB * NC) return;
    const int n = idx / NC, c = idx % NC;
    const float inv = 1.f / 12544.f;
    float s = bf[c];
    const float* sp = g_S + n * CF;
    const float* wp = Wf + (size_t)c * CF;
#pragma unroll 4
    for (int ch = 0; ch < CF; ++ch) s += (sp[ch] * inv) * wp[ch];
    out[idx] = s;
}

// ============================================================
// 4) top-2 per sample (serial scan; ties -> lower index first, like lax.top_k)
// ============================================================
__global__ void topk_kernel(const float* __restrict__ logits) {
    const int n = threadIdx.x;
    if (n >= NB) return;
    const float* lp = logits + n * NC;
    float v1 = -1e30f, v2 = -1e30f;
    int i1 = 0, i2 = 0;
    for (int c = 0; c < NC; ++c) {
        const float v = lp[c];
        if (v > v1) { v2 = v1; i2 = i1; v1 = v; i1 = c; }
        else if (v > v2) { v2 = v; i2 = c; }
    }
    g_labels[n * 2 + 0] = i1;
    g_labels[n * 2 + 1] = i2;
}

// ============================================================
// 5) per-(n,k,ch) GradCAM++ channel weights (G is spatially constant!)
//    g = Wf[l,ch]/P ; denom = 2g^2 + g^3*S + eps ; w = P*(g^2/denom)*relu(g)
//    Also (re)initialize the min/max atomics.
// ============================================================
__global__ void wgt_kernel(const float* __restrict__ Wf) {
    const int nk = blockIdx.x, ch = threadIdx.x;   // grid 32, block 128
    if (ch == 0) { g_mm[nk * 2] = 0x7f800000u; g_mm[nk * 2 + 1] = 0u; }
    const int n = nk >> 1;
    const int l = g_labels[nk];
    const float g  = Wf[(size_t)l * CF + ch] * (1.f / 12544.f);
    const float s  = g_S[n * CF + ch];
    const float g2 = g * g;
    const float denom = 2.f * g2 + g2 * g * s + EPSF;
    const float alpha = g2 / denom;
    g_wgt[nk * CF + ch] = 12544.f * alpha * fmaxf(g, 0.f);
}

// ============================================================
// 6) cam[n,k,:,:] = relu(sum_ch wgt*A); both k in one pass over A.
//    Per-map min/max via block reduce + uint atomics (cam >= 0).
// ============================================================
__global__ void cam_kernel() {
    const int n = blockIdx.y;
    const int p = blockIdx.x * 256 + threadIdx.x;   // grid.x=49 -> exactly 12544
    __shared__ float w0s[CF], w1s[CF];
    if (threadIdx.x < CF) {
        w0s[threadIdx.x] = g_wgt[(n * 2 + 0) * CF + threadIdx.x];
        w1s[threadIdx.x] = g_wgt[(n * 2 + 1) * CF + threadIdx.x];
    }
    __syncthreads();
    const float* Ap = g_A + (size_t)n * CF * P_SP + p;
    float a0 = 0.f, a1 = 0.f;
#pragma unroll 4
    for (int ch = 0; ch < CF; ++ch) {
        const float a = Ap[(size_t)ch * P_SP];
        a0 += w0s[ch] * a;
        a1 += w1s[ch] * a;
    }
    const float c0 = fmaxf(a0, 0.f), c1 = fmaxf(a1, 0.f);
    g_cam[(size_t)(n * 2 + 0) * P_SP + p] = c0;
    g_cam[(size_t)(n * 2 + 1) * P_SP + p] = c1;

    float mn0 = c0, mx0 = c0, mn1 = c1, mx1 = c1;
#pragma unroll
    for (int o = 16; o; o >>= 1) {
        mn0 = fminf(mn0, __shfl_xor_sync(0xffffffffu, mn0, o));
        mx0 = fmaxf(mx0, __shfl_xor_sync(0xffffffffu, mx0, o));
        mn1 = fminf(mn1, __shfl_xor_sync(0xffffffffu, mn1, o));
        mx1 = fmaxf(mx1, __shfl_xor_sync(0xffffffffu, mx1, o));
    }
    __shared__ float smn0[8], smx0[8], smn1[8], smx1[8];
    const int w = threadIdx.x >> 5, l = threadIdx.x & 31;
    if (l == 0) { smn0[w] = mn0; smx0[w] = mx0; smn1[w] = mn1; smx1[w] = mx1; }
    __syncthreads();
    if (threadIdx.x == 0) {
        float a = smn0[0], b = smx0[0], c = smn1[0], d = smx1[0];
#pragma unroll
        for (int i = 1; i < 8; ++i) {
            a = fminf(a, smn0[i]); b = fmaxf(b, smx0[i]);
            c = fminf(c, smn1[i]); d = fmaxf(d, smx1[i]);
        }
        atomicMin(&g_mm[(n * 2 + 0) * 2 + 0], __float_as_uint(a));
        atomicMax(&g_mm[(n * 2 + 0) * 2 + 1], __float_as_uint(b));
        atomicMin(&g_mm[(n * 2 + 1) * 2 + 0], __float_as_uint(c));
        atomicMax(&g_mm[(n * 2 + 1) * 2 + 1], __float_as_uint(d));
    }
}

// ============================================================
// 7) normalize + bilinear x2 upsample (half-pixel, clamped edges)
//    + threshold 0.35 + bbox/count/sum reduce + write tail outputs.
//    One block per (n,k).
// ============================================================
__global__ void final_kernel(float* __restrict__ out) {
    const int nk = blockIdx.x;                    // grid 32, block 256
    const int tid = threadIdx.x;
    const float mn = __uint_as_float(g_mm[nk * 2 + 0]);
    const float mx = __uint_as_float(g_mm[nk * 2 + 1]);
    const float inv = 1.f / (mx - mn + EPSF);
    const float* cm = g_cam + (size_t)nk * P_SP;

    int minx = 1 << 29, miny = 1 << 29, maxx = -1, maxy = -1, cnt = 0;
    float sum = 0.f;
    for (int p = tid; p < 224 * 224; p += 256) {
        const int dy = p / 224, dx = p % 224;
        float sy = fmaxf(0.5f * (float)dy - 0.25f, 0.f);
        float sx = fmaxf(0.5f * (float)dx - 0.25f, 0.f);
        int iy = (int)sy; float fy = sy - (float)iy; int iy1 = min(iy + 1, 111);
        int ix = (int)sx; float fx = sx - (float)ix; int ix1 = min(ix + 1, 111);
        iy = min(iy, 111); ix = min(ix, 111);
        const float c00 = (cm[iy  * 112 + ix ] - mn) * inv;
        const float c01 = (cm[iy  * 112 + ix1] - mn) * inv;
        const float c10 = (cm[iy1 * 112 + ix ] - mn) * inv;
        const float c11 = (cm[iy1 * 112 + ix1] - mn) * inv;
        const float v = (1.f - fy) * ((1.f - fx) * c00 + fx * c01)
                      +        fy  * ((1.f - fx) * c10 + fx * c11);
        if (v >= 0.35f) {
            ++cnt; sum += v;
            minx = min(minx, dx); maxx = max(maxx, dx);
            miny = min(miny, dy); maxy = max(maxy, dy);
        }
    }

    __shared__ int   ri[256];
    __shared__ float rf[256];
    // minx
    ri[tid] = minx; __syncthreads();
    for (int s = 128; s; s >>= 1) { if (tid < s) ri[tid] = min(ri[tid], ri[tid + s]); __syncthreads(); }
    minx = ri[0]; __syncthreads();
    // miny
    ri[tid] = miny; __syncthreads();
    for (int s = 128; s; s >>= 1) { if (tid < s) ri[tid] = min(ri[tid], ri[tid + s]); __syncthreads(); }
    miny = ri[0]; __syncthreads();
    // maxx
    ri[tid] = maxx; __syncthreads();
    for (int s = 128; s; s >>= 1) { if (tid < s) ri[tid] = max(ri[tid], ri[tid + s]); __syncthreads(); }
    maxx = ri[0]; __syncthreads();
    // maxy
    ri[tid] = maxy; __syncthreads();
    for (int s = 128; s; s >>= 1) { if (tid < s) ri[tid] = max(ri[tid], ri[tid + s]); __syncthreads(); }
    maxy = ri[0]; __syncthreads();
    // cnt
    ri[tid] = cnt; __syncthreads();
    for (int s = 128; s; s >>= 1) { if (tid < s) ri[tid] += ri[tid + s]; __syncthreads(); }
    cnt = ri[0]; __syncthreads();
    // sum
    rf[tid] = sum; __syncthreads();
    for (int s = 128; s; s >>= 1) { if (tid < s) rf[tid] += rf[tid + s]; __syncthreads(); }
    sum = rf[0];

    if (tid == 0) {
        const bool valid = (cnt > 0);
        float* boxes = out + 16000;
        boxes[nk * 4 + 0] = valid ? (float)minx : -1.f;
        boxes[nk * 4 + 1] = valid ? (float)miny : -1.f;
        boxes[nk * 4 + 2] = valid ? (float)maxx : -1.f;
        boxes[nk * 4 + 3] = valid ? (float)maxy : -1.f;
        out[16128 + nk] = (float)g_labels[nk];                     // labels
        out[16160 + nk] = valid ? sum / (float)cnt : 0.f;          // scores
        out[16192 + nk] = valid ? 1.f : 0.f;                       // valid
    }
}

// ============================================================
extern "C" void kernel_launch(void* const* d_in, const int* in_sizes, int n_in,
                              void* d_out, int out_size) {
    const float* x  = (const float*)d_in[0];
    const float* Wc = (const float*)d_in[1];
    const float* bc = (const float*)d_in[2];
    const float* Wf = (const float*)d_in[3];
    const float* bf = (const float*)d_in[4];
    float* out = (float*)d_out;

    conv_kernel<<<dim3(49, 16, 16), 64>>>(x, Wc, bc);
    gap_kernel<<<NB * CF, 256>>>();
    logits_kernel<<<(NB * NC + 255) / 256, 256>>>(Wf, bf, out);
    topk_kernel<<<1, 32>>>(out);
    wgt_kernel<<<NB * 2, CF>>>(Wf);
    cam_kernel<<<dim3(49, NB), 256>>>();
    final_kernel<<<NB * 2, 256>>>(out);
}

// round 3
// speedup vs baseline: 1.4809x; 1.4809x over previous
#include <cuda_runtime.h>
#include <cstdint>

#define HFD 112
#define WFD 112
#define P_SP 12544     // 112*112
#define CIN 32
#define CF 128
#define NB 16
#define NC 1000
#define EPSF 1e-6f
#define IN_STRIDE 40   // 33 cols padded; multiple of 4 for float4 LDS

// ---- scratch (static device globals; no allocation) ----
__device__ float    g_A[(size_t)NB * CF * P_SP];   // conv activations (with bias)
__device__ float    g_Spart[(size_t)NB * CF * 49]; // per-tile partial sums (no bias)
__device__ float    g_S[NB * CF];                  // spatial sums per channel
__device__ int      g_labels[NB * 2];
__device__ float    g_wgt[NB * 2 * CF];
__device__ float    g_cam[(size_t)NB * 2 * P_SP];
__device__ unsigned g_mm[NB * 2 * 2];              // [nk][0]=min bits, [1]=max bits

__device__ __forceinline__ void cp4(uint32_t d, const float* s, int sz) {
    asm volatile("cp.async.ca.shared.global [%0], [%1], 4, %2;\n"
                 :: "r"(d), "l"(s), "r"(sz));
}

// ============================================================
// 1) 3x3 stride-2 SAME conv, fp32, cp.async double-buffered.
//    Block: 64 threads, tile = 16x16 outputs x 16 filters.
//    Each thread: 4 consecutive x-outputs, 1 row, 16 filters -> 64 acc.
//    Epilogue: per-block per-filter partial spatial sums -> g_Spart.
// ============================================================
__global__ __launch_bounds__(64) void conv_kernel(const float* __restrict__ x,
                                                  const float* __restrict__ Wc,
                                                  const float* __restrict__ bc) {
    __shared__ __align__(16) float sIn[2][33 * IN_STRIDE];
    __shared__ float sW[16 * 32 * 9];
    __shared__ float sred[2][16];

    const int tid = threadIdx.x;
    const int txT = blockIdx.x % 7, tyT = blockIdx.x / 7;
    const int cfg = blockIdx.y;     // 0..7, 16 filters each
    const int n   = blockIdx.z;

    // stage weights for this block's 16 filters (all 32 cin) -- contiguous copy
    const float* wsrc = Wc + (size_t)cfg * 16 * 32 * 9;
    for (int i = tid; i < 16 * 32 * 9; i += 64) sW[i] = wsrc[i];

    const int ihb = tyT * 32, iwb = txT * 32;

    // precompute staging offsets: thread handles i = tid + 64k, k=0..16 (i<1088),
    // plus i=1088 handled by tid==0.
    int      goff[17];   // global offset within channel plane, or -1 if OOB (pad)
    uint32_t soff[17];   // smem byte offset within a buffer
#pragma unroll
    for (int k = 0; k < 17; ++k) {
        const int i = tid + 64 * k;
        const int r = i / 33, c = i - r * 33;
        const int gr = ihb + r, gc = iwb + c;
        goff[k] = (gr < 224 && gc < 224) ? (gr * 224 + gc) : -1;
        soff[k] = (uint32_t)(r * IN_STRIDE + c) * 4u;
    }
    int g_extra = -1;
    uint32_t s_extra = 0;
    if (tid == 0) {   // i = 1088 -> r=32, c=32
        const int gr = ihb + 32, gc = iwb + 32;
        g_extra = (gr < 224 && gc < 224) ? (gr * 224 + gc) : -1;
        s_extra = (uint32_t)(32 * IN_STRIDE + 32) * 4u;
    }

    uint32_t sb[2];
    sb[0] = (uint32_t)__cvta_generic_to_shared(&sIn[0][0]);
    sb[1] = (uint32_t)__cvta_generic_to_shared(&sIn[1][0]);

    const float* xb = x + (size_t)n * CIN * 224 * 224;

    // prologue: issue cin 0 into buffer 0
    {
        const float* xc = xb;
#pragma unroll
        for (int k = 0; k < 17; ++k)
            cp4(sb[0] + soff[k], xc + (goff[k] >= 0 ? goff[k] : 0), goff[k] >= 0 ? 4 : 0);
        if (tid == 0)
            cp4(sb[0] + s_extra, xc + (g_extra >= 0 ? g_extra : 0), g_extra >= 0 ? 4 : 0);
        asm volatile("cp.async.commit_group;\n");
    }

    float acc[16][4];
#pragma unroll
    for (int f = 0; f < 16; ++f)
#pragma unroll
        for (int j = 0; j < 4; ++j) acc[f][j] = 0.f;

    const int ty = tid >> 2, txg = tid & 3;

    for (int cin = 0; cin < CIN; ++cin) {
        __syncthreads();   // all threads done computing from buf[(cin+1)&1] (iter cin-1)
        if (cin + 1 < CIN) {
            const float* xc = xb + (size_t)(cin + 1) * 224 * 224;
            const uint32_t b = sb[(cin + 1) & 1];
#pragma unroll
            for (int k = 0; k < 17; ++k)
                cp4(b + soff[k], xc + (goff[k] >= 0 ? goff[k] : 0), goff[k] >= 0 ? 4 : 0);
            if (tid == 0)
                cp4(b + s_extra, xc + (g_extra >= 0 ? g_extra : 0), g_extra >= 0 ? 4 : 0);
            asm volatile("cp.async.commit_group;\n");
            asm volatile("cp.async.wait_group 1;\n");   // cin's group complete
        } else {
            asm volatile("cp.async.wait_group 0;\n");
        }
        __syncthreads();   // cin's buffer visible to all threads

        const float* inb = &sIn[cin & 1][(2 * ty) * IN_STRIDE + 8 * txg];
#pragma unroll
        for (int r = 0; r < 3; ++r) {
            const float4 v0 = *(const float4*)(inb + r * IN_STRIDE);
            const float4 v1 = *(const float4*)(inb + r * IN_STRIDE + 4);
            const float  v8 = inb[r * IN_STRIDE + 8];
            const float in0 = v0.x, in1 = v0.y, in2 = v0.z, in3 = v0.w;
            const float in4 = v1.x, in5 = v1.y, in6 = v1.z, in7 = v1.w;
#pragma unroll
            for (int f = 0; f < 16; ++f) {
                const float* wp = &sW[(f * 32 + cin) * 9 + 3 * r];  // warp-broadcast
                const float w0 = wp[0], w1 = wp[1], w2 = wp[2];
                acc[f][0] += w0 * in0 + w1 * in1 + w2 * in2;
                acc[f][1] += w0 * in2 + w1 * in3 + w2 * in4;
                acc[f][2] += w0 * in4 + w1 * in5 + w2 * in6;
                acc[f][3] += w0 * in6 + w1 * in7 + w2 * v8;
            }
        }
    }

    // store outputs (+bias) and per-filter partial sums (no bias)
    const int oy = tyT * 16 + ty, oxb = txT * 16 + 4 * txg;
    float psum[16];
#pragma unroll
    for (int f = 0; f < 16; ++f) {
        const int cf = cfg * 16 + f;
        const float b = bc[cf];
        float4 o = make_float4(acc[f][0] + b, acc[f][1] + b, acc[f][2] + b, acc[f][3] + b);
        *(float4*)&g_A[((size_t)(n * CF + cf) * HFD + oy) * WFD + oxb] = o;
        psum[f] = acc[f][0] + acc[f][1] + acc[f][2] + acc[f][3];
    }
#pragma unroll
    for (int f = 0; f < 16; ++f)
#pragma unroll
        for (int o = 16; o; o >>= 1)
            psum[f] += __shfl_xor_sync(0xffffffffu, psum[f], o);
    const int wid = tid >> 5, lid = tid & 31;
    if (lid == 0) {
#pragma unroll
        for (int f = 0; f < 16; ++f) sred[wid][f] = psum[f];
    }
    __syncthreads();
    if (tid < 16)
        g_Spart[(size_t)(n * CF + cfg * 16 + tid) * 49 + blockIdx.x] =
            sred[0][tid] + sred[1][tid];
}

// ============================================================
// 2) reduce partial sums: S[n,cf] = sum_tiles + 12544*bc[cf]
// ============================================================
__global__ void gap_kernel(const float* __restrict__ bc) {
    const int idx = blockIdx.x * 256 + threadIdx.x;
    if (idx >= NB * CF) return;
    const float* p = g_Spart + (size_t)idx * 49;
    float s = 0.f;
#pragma unroll
    for (int i = 0; i < 49; ++i) s += p[i];
    g_S[idx] = s + 12544.f * bc[idx % CF];
}

// ============================================================
// 3) logits[n,c] = mean(A) . Wf[c,:] + bf[c]  -> d_out[0:16000]
// ============================================================
__global__ void logits_kernel(const float* __restrict__ Wf, const float* __restrict__ bf,
                              float* __restrict__ out) {
    const int idx = blockIdx.x * 256 + threadIdx.x;
    if (idx >= NB * NC) return;
    const int n = idx / NC, c = idx % NC;
    const float inv = 1.f / 12544.f;
    float s = bf[c];
    const float* sp = g_S + n * CF;
    const float* wp = Wf + (size_t)c * CF;
#pragma unroll 4
    for (int ch = 0; ch < CF; ++ch) s += (sp[ch] * inv) * wp[ch];
    out[idx] = s;
}

// ============================================================
// 4) top-2 per sample, parallel. One block per n.
//    Tie-break: lower index wins (matches lax.top_k).
// ============================================================
__global__ void topk_kernel(const float* __restrict__ logits) {
    const int n = blockIdx.x, tid = threadIdx.x;   // block 256
    const float* lp = logits + n * NC;
    float v1 = -3.4e38f, v2 = -3.4e38f;
    int i1 = NC, i2 = NC;
    for (int c = tid; c < NC; c += 256) {
        const float v = lp[c];     // c ascending => strict > keeps earliest index
        if (v > v1) { v2 = v1; i2 = i1; v1 = v; i1 = c; }
        else if (v > v2) { v2 = v; i2 = c; }
    }
    __shared__ float sv1[256], sv2[256];
    __shared__ int   si1[256], si2[256];
    sv1[tid] = v1; sv2[tid] = v2; si1[tid] = i1; si2[tid] = i2;
    __syncthreads();
    if (tid == 0) {
        float b1 = -3.4e38f, b2 = -3.4e38f;
        int j1 = NC, j2 = NC;
        for (int t = 0; t < 256; ++t) {
#pragma unroll
            for (int s = 0; s < 2; ++s) {
                const float v = s ? sv2[t] : sv1[t];
                const int   i = s ? si2[t] : si1[t];
                if (v > b1 || (v == b1 && i < j1)) {
                    b2 = b1; j2 = j1; b1 = v; j1 = i;
                } else if (v > b2 || (v == b2 && i < j2)) {
                    b2 = v; j2 = i;
                }
            }
        }
        g_labels[n * 2 + 0] = j1;
        g_labels[n * 2 + 1] = j2;
    }
}

// ============================================================
// 5) per-(n,k,ch) GradCAM++ channel weights (G spatially constant)
// ============================================================
__global__ void wgt_kernel(const float* __restrict__ Wf) {
    const int nk = blockIdx.x, ch = threadIdx.x;   // grid 32, block 128
    if (ch == 0) { g_mm[nk * 2] = 0x7f800000u; g_mm[nk * 2 + 1] = 0u; }
    const int n = nk >> 1;
    const int l = g_labels[nk];
    const float g  = Wf[(size_t)l * CF + ch] * (1.f / 12544.f);
    const float s  = g_S[n * CF + ch];
    const float g2 = g * g;
    const float denom = 2.f * g2 + g2 * g * s + EPSF;
    const float alpha = g2 / denom;
    g_wgt[nk * CF + ch] = 12544.f * alpha * fmaxf(g, 0.f);
}

// ============================================================
// 6) cam = relu(sum_ch wgt*A), both k per pass; min/max via atomics
// ============================================================
__global__ void cam_kernel() {
    const int n = blockIdx.y;
    const int p = blockIdx.x * 256 + threadIdx.x;   // grid.x=49 -> exactly 12544
    __shared__ float w0s[CF], w1s[CF];
    if (threadIdx.x < CF) {
        w0s[threadIdx.x] = g_wgt[(n * 2 + 0) * CF + threadIdx.x];
        w1s[threadIdx.x] = g_wgt[(n * 2 + 1) * CF + threadIdx.x];
    }
    __syncthreads();
    const float* Ap = g_A + (size_t)n * CF * P_SP + p;
    float a0 = 0.f, a1 = 0.f;
#pragma unroll 4
    for (int ch = 0; ch < CF; ++ch) {
        const float a = Ap[(size_t)ch * P_SP];
        a0 += w0s[ch] * a;
        a1 += w1s[ch] * a;
    }
    const float c0 = fmaxf(a0, 0.f), c1 = fmaxf(a1, 0.f);
    g_cam[(size_t)(n * 2 + 0) * P_SP + p] = c0;
    g_cam[(size_t)(n * 2 + 1) * P_SP + p] = c1;

    float mn0 = c0, mx0 = c0, mn1 = c1, mx1 = c1;
#pragma unroll
    for (int o = 16; o; o >>= 1) {
        mn0 = fminf(mn0, __shfl_xor_sync(0xffffffffu, mn0, o));
        mx0 = fmaxf(mx0, __shfl_xor_sync(0xffffffffu, mx0, o));
        mn1 = fminf(mn1, __shfl_xor_sync(0xffffffffu, mn1, o));
        mx1 = fmaxf(mx1, __shfl_xor_sync(0xffffffffu, mx1, o));
    }
    __shared__ float smn0[8], smx0[8], smn1[8], smx1[8];
    const int w = threadIdx.x >> 5, l = threadIdx.x & 31;
    if (l == 0) { smn0[w] = mn0; smx0[w] = mx0; smn1[w] = mn1; smx1[w] = mx1; }
    __syncthreads();
    if (threadIdx.x == 0) {
        float a = smn0[0], b = smx0[0], c = smn1[0], d = smx1[0];
#pragma unroll
        for (int i = 1; i < 8; ++i) {
            a = fminf(a, smn0[i]); b = fmaxf(b, smx0[i]);
            c = fminf(c, smn1[i]); d = fmaxf(d, smx1[i]);
        }
        atomicMin(&g_mm[(n * 2 + 0) * 2 + 0], __float_as_uint(a));
        atomicMax(&g_mm[(n * 2 + 0) * 2 + 1], __float_as_uint(b));
        atomicMin(&g_mm[(n * 2 + 1) * 2 + 0], __float_as_uint(c));
        atomicMax(&g_mm[(n * 2 + 1) * 2 + 1], __float_as_uint(d));
    }
}

// ============================================================
// 7) normalize + bilinear x2 upsample + threshold + bbox/score
// ============================================================
__global__ void final_kernel(float* __restrict__ out) {
    const int nk = blockIdx.x;                    // grid 32, block 256
    const int tid = threadIdx.x;
    const float mn = __uint_as_float(g_mm[nk * 2 + 0]);
    const float mx = __uint_as_float(g_mm[nk * 2 + 1]);
    const float inv = 1.f / (mx - mn + EPSF);
    const float* cm = g_cam + (size_t)nk * P_SP;

    int minx = 1 << 29, miny = 1 << 29, maxx = -1, maxy = -1, cnt = 0;
    float sum = 0.f;
    for (int p = tid; p < 224 * 224; p += 256) {
        const int dy = p / 224, dx = p % 224;
        float sy = fmaxf(0.5f * (float)dy - 0.25f, 0.f);
        float sx = fmaxf(0.5f * (float)dx - 0.25f, 0.f);
        int iy = (int)sy; float fy = sy - (float)iy; int iy1 = min(iy + 1, 111);
        int ix = (int)sx; float fx = sx - (float)ix; int ix1 = min(ix + 1, 111);
        iy = min(iy, 111); ix = min(ix, 111);
        const float c00 = (cm[iy  * 112 + ix ] - mn) * inv;
        const float c01 = (cm[iy  * 112 + ix1] - mn) * inv;
        const float c10 = (cm[iy1 * 112 + ix ] - mn) * inv;
        const float c11 = (cm[iy1 * 112 + ix1] - mn) * inv;
        const float v = (1.f - fy) * ((1.f - fx) * c00 + fx * c01)
                      +        fy  * ((1.f - fx) * c10 + fx * c11);
        if (v >= 0.35f) {
            ++cnt; sum += v;
            minx = min(minx, dx); maxx = max(maxx, dx);
            miny = min(miny, dy); maxy = max(maxy, dy);
        }
    }

    __shared__ int   ri[256];
    __shared__ float rf[256];
    ri[tid] = minx; __syncthreads();
    for (int s = 128; s; s >>= 1) { if (tid < s) ri[tid] = min(ri[tid], ri[tid + s]); __syncthreads(); }
    minx = ri[0]; __syncthreads();
    ri[tid] = miny; __syncthreads();
    for (int s = 128; s; s >>= 1) { if (tid < s) ri[tid] = min(ri[tid], ri[tid + s]); __syncthreads(); }
    miny = ri[0]; __syncthreads();
    ri[tid] = maxx; __syncthreads();
    for (int s = 128; s; s >>= 1) { if (tid < s) ri[tid] = max(ri[tid], ri[tid + s]); __syncthreads(); }
    maxx = ri[0]; __syncthreads();
    ri[tid] = maxy; __syncthreads();
    for (int s = 128; s; s >>= 1) { if (tid < s) ri[tid] = max(ri[tid], ri[tid + s]); __syncthreads(); }
    maxy = ri[0]; __syncthreads();
    ri[tid] = cnt; __syncthreads();
    for (int s = 128; s; s >>= 1) { if (tid < s) ri[tid] += ri[tid + s]; __syncthreads(); }
    cnt = ri[0]; __syncthreads();
    rf[tid] = sum; __syncthreads();
    for (int s = 128; s; s >>= 1) { if (tid < s) rf[tid] += rf[tid + s]; __syncthreads(); }
    sum = rf[0];

    if (tid == 0) {
        const bool valid = (cnt > 0);
        float* boxes = out + 16000;
        boxes[nk * 4 + 0] = valid ? (float)minx : -1.f;
        boxes[nk * 4 + 1] = valid ? (float)miny : -1.f;
        boxes[nk * 4 + 2] = valid ? (float)maxx : -1.f;
        boxes[nk * 4 + 3] = valid ? (float)maxy : -1.f;
        out[16128 + nk] = (float)g_labels[nk];
        out[16160 + nk] = valid ? sum / (float)cnt : 0.f;
        out[16192 + nk] = valid ? 1.f : 0.f;
    }
}

// ============================================================
extern "C" void kernel_launch(void* const* d_in, const int* in_sizes, int n_in,
                              void* d_out, int out_size) {
    const float* x  = (const float*)d_in[0];
    const float* Wc = (const float*)d_in[1];
    const float* bc = (const float*)d_in[2];
    const float* Wf = (const float*)d_in[3];
    const float* bf = (const float*)d_in[4];
    float* out = (float*)d_out;

    conv_kernel<<<dim3(49, 8, 16), 64>>>(x, Wc, bc);
    gap_kernel<<<8, 256>>>(bc);
    logits_kernel<<<(NB * NC + 255) / 256, 256>>>(Wf, bf, out);
    topk_kernel<<<NB, 256>>>(out);
    wgt_kernel<<<NB * 2, CF>>>(Wf);
    cam_kernel<<<dim3(49, NB), 256>>>();
    final_kernel<<<NB * 2, 256>>>(out);
}

// round 5
// speedup vs baseline: 1.9188x; 1.2957x over previous
#include <cuda_runtime.h>
#include <cstdint>

#define HFD 112
#define WFD 112
#define P_SP 12544     // 112*112
#define CIN 32
#define CF 128
#define NB 16
#define NC 1000
#define EPSF 1e-6f
#define IN_STRIDE 40   // 36 cols used of 40; multiple of 4 for float4

// ---- scratch (static device globals; no allocation) ----
__device__ float    g_A[(size_t)NB * CF * P_SP];   // conv activations (with bias)
__device__ float    g_Spart[(size_t)NB * CF * 49]; // per-tile partial sums (no bias)
__device__ float    g_S[NB * CF];                  // spatial sums per channel
__device__ int      g_labels[NB * 2];
__device__ float    g_wgt[NB * 2 * CF];
__device__ float    g_cam[(size_t)NB * 2 * P_SP];
__device__ unsigned g_mm[NB * 2 * 2];              // [nk][0]=min bits, [1]=max bits

__device__ __forceinline__ void cp16(uint32_t d, const float* s, int src_bytes) {
    asm volatile("cp.async.cg.shared.global [%0], [%1], 16, %2;\n"
                 :: "r"(d), "l"(s), "r"(src_bytes));
}

// ============================================================
// 1) 3x3 stride-2 SAME conv, fp32, cp.async(16B,zfill) double-buffered.
//    Block: 64 threads, tile = 16x16 outputs x 16 filters.
//    Each thread: 4 consecutive x-outputs, 1 row, 16 filters -> 64 acc.
//    Weights padded to float4 per (f,cin,row) -> LDS.128 only.
//    Epilogue: per-block per-filter partial spatial sums -> g_Spart.
// ============================================================
__global__ __launch_bounds__(64) void conv_kernel(const float* __restrict__ x,
                                                  const float* __restrict__ Wc,
                                                  const float* __restrict__ bc) {
    __shared__ __align__(16) float  sIn[2][33 * IN_STRIDE];
    __shared__ __align__(16) float4 sW4[16 * 32 * 3];   // (f,cin,row) -> {w0,w1,w2,pad}
    __shared__ float sred[2][16];

    const int tid = threadIdx.x;
    const int txT = blockIdx.x % 7, tyT = blockIdx.x / 7;
    const int cfg = blockIdx.y;     // 0..7, 16 filters each
    const int n   = blockIdx.z;

    // stage weights for this block's 16 filters (all 32 cin), padded layout
    {
        const float* wsrc = Wc + (size_t)cfg * 16 * 32 * 9;
        float* sWf = (float*)sW4;
        for (int i = tid; i < 16 * 32 * 9; i += 64) {
            const int f = i / 288, rem = i % 288, c = rem / 9, j = rem % 9;
            const int r = j / 3, col = j - 3 * r;
            sWf[(((f * 32 + c) * 3 + r) << 2) + col] = wsrc[i];
        }
    }

    const int ihb = tyT * 32, iwb = txT * 32;

    // staging plan: 33 rows x 9 float4-chunks (cols 0..35) = 297 chunks.
    // k=0..3 unconditional (i=tid+64k<256), k=4 only for tid<41.
    int      goff[5];
    int      vbytes[5];
    uint32_t soff[5];
#pragma unroll
    for (int k = 0; k < 5; ++k) {
        const int i = tid + 64 * k;
        const int r = i / 9, cb = i - 9 * r;
        const int gr = ihb + r, gc0 = iwb + cb * 4;
        int v = 0;
        if (i < 297 && gr < 224 && gc0 < 224) v = min(16, (224 - gc0) * 4);
        goff[k]   = v ? (gr * 224 + gc0) : 0;
        vbytes[k] = v;
        soff[k]   = (uint32_t)(r * IN_STRIDE + cb * 4) * 4u;
    }
    const bool has5 = (tid < 41);

    uint32_t sb[2];
    sb[0] = (uint32_t)__cvta_generic_to_shared(&sIn[0][0]);
    sb[1] = (uint32_t)__cvta_generic_to_shared(&sIn[1][0]);

    const float* xb = x + (size_t)n * CIN * 224 * 224;

    // prologue: issue cin 0 into buffer 0
    {
        const float* xc = xb;
#pragma unroll
        for (int k = 0; k < 4; ++k) cp16(sb[0] + soff[k], xc + goff[k], vbytes[k]);
        if (has5) cp16(sb[0] + soff[4], xc + goff[4], vbytes[4]);
        asm volatile("cp.async.commit_group;\n");
    }

    float acc[16][4];
#pragma unroll
    for (int f = 0; f < 16; ++f)
#pragma unroll
        for (int j = 0; j < 4; ++j) acc[f][j] = 0.f;

    const int ty = tid >> 2, txg = tid & 3;

    for (int cin = 0; cin < CIN; ++cin) {
        __syncthreads();   // everyone done with buf[(cin+1)&1] (iter cin-1); also weights staged
        if (cin + 1 < CIN) {
            const float* xc = xb + (size_t)(cin + 1) * 224 * 224;
            const uint32_t b = sb[(cin + 1) & 1];
#pragma unroll
            for (int k = 0; k < 4; ++k) cp16(b + soff[k], xc + goff[k], vbytes[k]);
            if (has5) cp16(b + soff[4], xc + goff[4], vbytes[4]);
            asm volatile("cp.async.commit_group;\n");
            asm volatile("cp.async.wait_group 1;\n");   // cin's group complete
        } else {
            asm volatile("cp.async.wait_group 0;\n");
        }
        __syncthreads();   // cin's buffer visible to all threads

        const float*  inb = &sIn[cin & 1][(2 * ty) * IN_STRIDE + 8 * txg];
        const float4* wq  = sW4 + cin * 3;              // + f*96 + r
#pragma unroll
        for (int r = 0; r < 3; ++r) {
            const float4 v0 = *(const float4*)(inb + r * IN_STRIDE);
            const float4 v1 = *(const float4*)(inb + r * IN_STRIDE + 4);
            const float  v8 = inb[r * IN_STRIDE + 8];
            const float in0 = v0.x, in1 = v0.y, in2 = v0.z, in3 = v0.w;
            const float in4 = v1.x, in5 = v1.y, in6 = v1.z, in7 = v1.w;
#pragma unroll
            for (int f = 0; f < 16; ++f) {
                const float4 w = wq[f * 96 + r];        // LDS.128, warp-broadcast
                acc[f][0] += w.x * in0 + w.y * in1 + w.z * in2;
                acc[f][1] += w.x * in2 + w.y * in3 + w.z * in4;
                acc[f][2] += w.x * in4 + w.y * in5 + w.z * in6;
                acc[f][3] += w.x * in6 + w.y * in7 + w.z * v8;
            }
        }
    }

    // store outputs (+bias) and per-filter partial sums (no bias)
    const int oy = tyT * 16 + ty, oxb = txT * 16 + 4 * txg;
    float psum[16];
#pragma unroll
    for (int f = 0; f < 16; ++f) {
        const int cf = cfg * 16 + f;
        const float b = bc[cf];
        float4 o = make_float4(acc[f][0] + b, acc[f][1] + b, acc[f][2] + b, acc[f][3] + b);
        *(float4*)&g_A[((size_t)(n * CF + cf) * HFD + oy) * WFD + oxb] = o;
        psum[f] = acc[f][0] + acc[f][1] + acc[f][2] + acc[f][3];
    }
#pragma unroll
    for (int f = 0; f < 16; ++f)
#pragma unroll
        for (int o = 16; o; o >>= 1)
            psum[f] += __shfl_xor_sync(0xffffffffu, psum[f], o);
    const int wid = tid >> 5, lid = tid & 31;
    if (lid == 0) {
#pragma unroll
        for (int f = 0; f < 16; ++f) sred[wid][f] = psum[f];
    }
    __syncthreads();
    if (tid < 16)
        g_Spart[(size_t)(n * CF + cfg * 16 + tid) * 49 + blockIdx.x] =
            sred[0][tid] + sred[1][tid];
}

// ============================================================
// 2) reduce partial sums: S[n,cf] = sum_tiles + 12544*bc[cf]
// ============================================================
__global__ void gap_kernel(const float* __restrict__ bc) {
    const int idx = blockIdx.x * 256 + threadIdx.x;
    if (idx >= NB * CF) return;
    const float* p = g_Spart + (size_t)idx * 49;
    float s = 0.f;
#pragma unroll
    for (int i = 0; i < 49; ++i) s += p[i];
    g_S[idx] = s + 12544.f * bc[idx % CF];
}

// ============================================================
// 3) logits[n,c] = mean(A) . Wf[c,:] + bf[c]  -> d_out[0:16000]
// ============================================================
__global__ void logits_kernel(const float* __restrict__ Wf, const float* __restrict__ bf,
                              float* __restrict__ out) {
    const int idx = blockIdx.x * 256 + threadIdx.x;
    if (idx >= NB * NC) return;
    const int n = idx / NC, c = idx % NC;
    const float inv = 1.f / 12544.f;
    float s = bf[c];
    const float* sp = g_S + n * CF;
    const float* wp = Wf + (size_t)c * CF;
#pragma unroll 4
    for (int ch = 0; ch < CF; ++ch) s += (sp[ch] * inv) * wp[ch];
    out[idx] = s;
}

// ============================================================
// 4) top-2 per sample, parallel + tree merge.
//    Tie-break: lower index wins (matches lax.top_k).
// ============================================================
__global__ void topk_kernel(const float* __restrict__ logits) {
    const int n = blockIdx.x, tid = threadIdx.x;   // block 256
    const float* lp = logits + n * NC;
    float v1 = -3.4e38f, v2 = -3.4e38f;
    int i1 = NC, i2 = NC;
    for (int c = tid; c < NC; c += 256) {
        const float v = lp[c];     // c ascending => strict > keeps earliest index
        if (v > v1) { v2 = v1; i2 = i1; v1 = v; i1 = c; }
        else if (v > v2) { v2 = v; i2 = c; }
    }
    __shared__ float sv1[256], sv2[256];
    __shared__ int   si1[256], si2[256];
    sv1[tid] = v1; sv2[tid] = v2; si1[tid] = i1; si2[tid] = i2;
    __syncthreads();
    for (int s = 128; s; s >>= 1) {
        if (tid < s) {
            const float a1 = sv1[tid],     a2 = sv2[tid];
            const int   ja1 = si1[tid],    ja2 = si2[tid];
            const float b1 = sv1[tid + s], b2 = sv2[tid + s];
            const int   jb1 = si1[tid + s], jb2 = si2[tid + s];
            float f1, f2; int j1, j2;
            if (b1 > a1 || (b1 == a1 && jb1 < ja1)) {
                f1 = b1; j1 = jb1;
                if (a1 > b2 || (a1 == b2 && ja1 < jb2)) { f2 = a1; j2 = ja1; }
                else                                    { f2 = b2; j2 = jb2; }
            } else {
                f1 = a1; j1 = ja1;
                if (b1 > a2 || (b1 == a2 && jb1 < ja2)) { f2 = b1; j2 = jb1; }
                else                                    { f2 = a2; j2 = ja2; }
            }
            sv1[tid] = f1; sv2[tid] = f2; si1[tid] = j1; si2[tid] = j2;
        }
        __syncthreads();
    }
    if (tid == 0) {
        g_labels[n * 2 + 0] = si1[0];
        g_labels[n * 2 + 1] = si2[0];
    }
}

// ============================================================
// 5) per-(n,k,ch) GradCAM++ channel weights (G spatially constant)
// ============================================================
__global__ void wgt_kernel(const float* __restrict__ Wf) {
    const int nk = blockIdx.x, ch = threadIdx.x;   // grid 32, block 128
    if (ch == 0) { g_mm[nk * 2] = 0x7f800000u; g_mm[nk * 2 + 1] = 0u; }
    const int n = nk >> 1;
    const int l = g_labels[nk];
    const float g  = Wf[(size_t)l * CF + ch] * (1.f / 12544.f);
    const float s  = g_S[n * CF + ch];
    const float g2 = g * g;
    const float denom = 2.f * g2 + g2 * g * s + EPSF;
    const float alpha = g2 / denom;
    g_wgt[nk * CF + ch] = 12544.f * alpha * fmaxf(g, 0.f);
}

// ============================================================
// 6) cam = relu(sum_ch wgt*A), both k per pass; min/max via atomics
// ============================================================
__global__ void cam_kernel() {
    const int n = blockIdx.y;
    const int p = blockIdx.x * 256 + threadIdx.x;   // grid.x=49 -> exactly 12544
    __shared__ float w0s[CF], w1s[CF];
    if (threadIdx.x < CF) {
        w0s[threadIdx.x] = g_wgt[(n * 2 + 0) * CF + threadIdx.x];
        w1s[threadIdx.x] = g_wgt[(n * 2 + 1) * CF + threadIdx.x];
    }
    __syncthreads();
    const float* Ap = g_A + (size_t)n * CF * P_SP + p;
    float a0 = 0.f, a1 = 0.f;
#pragma unroll 4
    for (int ch = 0; ch < CF; ++ch) {
        const float a = Ap[(size_t)ch * P_SP];
        a0 += w0s[ch] * a;
        a1 += w1s[ch] * a;
    }
    const float c0 = fmaxf(a0, 0.f), c1 = fmaxf(a1, 0.f);
    g_cam[(size_t)(n * 2 + 0) * P_SP + p] = c0;
    g_cam[(size_t)(n * 2 + 1) * P_SP + p] = c1;

    float mn0 = c0, mx0 = c0, mn1 = c1, mx1 = c1;
#pragma unroll
    for (int o = 16; o; o >>= 1) {
        mn0 = fminf(mn0, __shfl_xor_sync(0xffffffffu, mn0, o));
        mx0 = fmaxf(mx0, __shfl_xor_sync(0xffffffffu, mx0, o));
        mn1 = fminf(mn1, __shfl_xor_sync(0xffffffffu, mn1, o));
        mx1 = fmaxf(mx1, __shfl_xor_sync(0xffffffffu, mx1, o));
    }
    __shared__ float smn0[8], smx0[8], smn1[8], smx1[8];
    const int w = threadIdx.x >> 5, l = threadIdx.x & 31;
    if (l == 0) { smn0[w] = mn0; smx0[w] = mx0; smn1[w] = mn1; smx1[w] = mx1; }
    __syncthreads();
    if (threadIdx.x == 0) {
        float a = smn0[0], b = smx0[0], c = smn1[0], d = smx1[0];
#pragma unroll
        for (int i = 1; i < 8; ++i) {
            a = fminf(a, smn0[i]); b = fmaxf(b, smx0[i]);
            c = fminf(c, smn1[i]); d = fmaxf(d, smx1[i]);
        }
        atomicMin(&g_mm[(n * 2 + 0) * 2 + 0], __float_as_uint(a));
        atomicMax(&g_mm[(n * 2 + 0) * 2 + 1], __float_as_uint(b));
        atomicMin(&g_mm[(n * 2 + 1) * 2 + 0], __float_as_uint(c));
        atomicMax(&g_mm[(n * 2 + 1) * 2 + 1], __float_as_uint(d));
    }
}

// ============================================================
// 7) normalize + bilinear x2 upsample + threshold + bbox/score
// ============================================================
__global__ void final_kernel(float* __restrict__ out) {
    const int nk = blockIdx.x;                    // grid 32, block 256
    const int tid = threadIdx.x;
    const float mn = __uint_as_float(g_mm[nk * 2 + 0]);
    const float mx = __uint_as_float(g_mm[nk * 2 + 1]);
    const float inv = 1.f / (mx - mn + EPSF);
    const float* cm = g_cam + (size_t)nk * P_SP;

    int minx = 1 << 29, miny = 1 << 29, maxx = -1, maxy = -1, cnt = 0;
    float sum = 0.f;
    for (int p = tid; p < 224 * 224; p += 256) {
        const int dy = p / 224, dx = p % 224;
        float sy = fmaxf(0.5f * (float)dy - 0.25f, 0.f);
        float sx = fmaxf(0.5f * (float)dx - 0.25f, 0.f);
        int iy = (int)sy; float fy = sy - (float)iy; int iy1 = min(iy + 1, 111);
        int ix = (int)sx; float fx = sx - (float)ix; int ix1 = min(ix + 1, 111);
        iy = min(iy, 111); ix = min(ix, 111);
        const float c00 = (cm[iy  * 112 + ix ] - mn) * inv;
        const float c01 = (cm[iy  * 112 + ix1] - mn) * inv;
        const float c10 = (cm[iy1 * 112 + ix ] - mn) * inv;
        const float c11 = (cm[iy1 * 112 + ix1] - mn) * inv;
        const float v = (1.f - fy) * ((1.f - fx) * c00 + fx * c01)
                      +        fy  * ((1.f - fx) * c10 + fx * c11);
        if (v >= 0.35f) {
            ++cnt; sum += v;
            minx = min(minx, dx); maxx = max(maxx, dx);
            miny = min(miny, dy); maxy = max(maxy, dy);
        }
    }

    __shared__ int   ri[256];
    __shared__ float rf[256];
    ri[tid] = minx; __syncthreads();
    for (int s = 128; s; s >>= 1) { if (tid < s) ri[tid] = min(ri[tid], ri[tid + s]); __syncthreads(); }
    minx = ri[0]; __syncthreads();
    ri[tid] = miny; __syncthreads();
    for (int s = 128; s; s >>= 1) { if (tid < s) ri[tid] = min(ri[tid], ri[tid + s]); __syncthreads(); }
    miny = ri[0]; __syncthreads();
    ri[tid] = maxx; __syncthreads();
    for (int s = 128; s; s >>= 1) { if (tid < s) ri[tid] = max(ri[tid], ri[tid + s]); __syncthreads(); }
    maxx = ri[0]; __syncthreads();
    ri[tid] = maxy; __syncthreads();
    for (int s = 128; s; s >>= 1) { if (tid < s) ri[tid] = max(ri[tid], ri[tid + s]); __syncthreads(); }
    maxy = ri[0]; __syncthreads();
    ri[tid] = cnt; __syncthreads();
    for (int s = 128; s; s >>= 1) { if (tid < s) ri[tid] += ri[tid + s]; __syncthreads(); }
    cnt = ri[0]; __syncthreads();
    rf[tid] = sum; __syncthreads();
    for (int s = 128; s; s >>= 1) { if (tid < s) rf[tid] += rf[tid + s]; __syncthreads(); }
    sum = rf[0];

    if (tid == 0) {
        const bool valid = (cnt > 0);
        float* boxes = out + 16000;
        boxes[nk * 4 + 0] = valid ? (float)minx : -1.f;
        boxes[nk * 4 + 1] = valid ? (float)miny : -1.f;
        boxes[nk * 4 + 2] = valid ? (float)maxx : -1.f;
        boxes[nk * 4 + 3] = valid ? (float)maxy : -1.f;
        out[16128 + nk] = (float)g_labels[nk];
        out[16160 + nk] = valid ? sum / (float)cnt : 0.f;
        out[16192 + nk] = valid ? 1.f : 0.f;
    }
}

// ============================================================
extern "C" void kernel_launch(void* const* d_in, const int* in_sizes, int n_in,
                              void* d_out, int out_size) {
    const float* x  = (const float*)d_in[0];
    const float* Wc = (const float*)d_in[1];
    const float* bc = (const float*)d_in[2];
    const float* Wf = (const float*)d_in[3];
    const float* bf = (const float*)d_in[4];
    float* out = (float*)d_out;

    conv_kernel<<<dim3(49, 8, 16), 64>>>(x, Wc, bc);
    gap_kernel<<<8, 256>>>(bc);
    logits_kernel<<<(NB * NC + 255) / 256, 256>>>(Wf, bf, out);
    topk_kernel<<<NB, 256>>>(out);
    wgt_kernel<<<NB * 2, CF>>>(Wf);
    cam_kernel<<<dim3(49, NB), 256>>>();
    final_kernel<<<NB * 2, 256>>>(out);
}

// round 6
// speedup vs baseline: 2.2840x; 1.1903x over previous
#include <cuda_runtime.h>
#include <cstdint>

#define HFD 112
#define WFD 112
#define P_SP 12544     // 112*112
#define CIN 32
#define CF 128
#define NB 16
#define NC 1000
#define EPSF 1e-6f
#define IN_STRIDE 40   // 36 cols used of 40; multiple of 4 for float4

// ---- scratch (static device globals; no allocation) ----
__device__ float    g_A[(size_t)NB * CF * P_SP];   // conv activations (with bias)
__device__ float    g_Spart[(size_t)NB * CF * 49]; // per-tile partial sums (no bias)
__device__ float    g_S[NB * CF];                  // spatial sums per channel
__device__ int      g_labels[NB * 2];
__device__ float    g_wgt[NB * 2 * CF];
__device__ float    g_cam[(size_t)NB * 2 * P_SP];
__device__ unsigned g_mm[NB * 2 * 2];              // [nk][0]=min bits, [1]=max bits

__device__ __forceinline__ void cp16(uint32_t d, const float* s, int src_bytes) {
    asm volatile("cp.async.cg.shared.global [%0], [%1], 16, %2;\n"
                 :: "r"(d), "l"(s), "r"(src_bytes));
}

// packed fp32x2 FMA (SASS FFMA2): d = a*b + d, two IEEE fp32 lanes
__device__ __forceinline__ void ffma2(unsigned long long& d,
                                      unsigned long long a, unsigned long long b) {
    asm("fma.rn.f32x2 %0, %1, %2, %0;" : "+l"(d) : "l"(a), "l"(b));
}
__device__ __forceinline__ unsigned long long pack2(float lo, float hi) {
    unsigned long long r;
    asm("mov.b64 %0, {%1, %2};" : "=l"(r) : "f"(lo), "f"(hi));
    return r;
}
__device__ __forceinline__ void unpack2(unsigned long long v, float& lo, float& hi) {
    asm("mov.b64 {%0, %1}, %2;" : "=f"(lo), "=f"(hi) : "l"(v));
}

// ============================================================
// 1) 3x3 stride-2 SAME conv, fp32, cp.async(16B,zfill) double-buffered,
//    packed-FFMA2 math: accumulators packed across adjacent filter pairs.
//    Block: 64 threads, tile = 16x16 outputs x 16 filters.
//    Each thread: 4 x-outputs x 8 filter-pairs -> 32 f32x2 accumulators.
//    Weights stored in smem pre-paired: (cin, r, col, fp) -> (W[2fp], W[2fp+1]).
//    Epilogue: per-block per-filter partial spatial sums -> g_Spart.
// ============================================================
__global__ __launch_bounds__(64) void conv_kernel(const float* __restrict__ x,
                                                  const float* __restrict__ Wc,
                                                  const float* __restrict__ bc) {
    __shared__ __align__(16) float sIn[2][33 * IN_STRIDE];
    __shared__ __align__(16) unsigned long long sW2[CIN * 3 * 3 * 8]; // [cin][r][col][fp]
    __shared__ float sred[2][16];

    const int tid = threadIdx.x;
    const int txT = blockIdx.x % 7, tyT = blockIdx.x / 7;
    const int cfg = blockIdx.y;     // 0..7, 16 filters each
    const int n   = blockIdx.z;

    // stage weights pre-paired across adjacent filters
    {
        const float* wsrc = Wc + (size_t)cfg * 16 * 32 * 9;
        float* sWf = (float*)sW2;
        for (int i = tid; i < 16 * 32 * 9; i += 64) {
            const int f = i / 288, rem = i % 288, c = rem / 9, j = rem % 9;
            const int r = j / 3, col = j - 3 * r;
            sWf[((((c * 3 + r) * 3 + col) * 8 + (f >> 1)) << 1) + (f & 1)] = wsrc[i];
        }
    }

    const int ihb = tyT * 32, iwb = txT * 32;

    // staging plan: 33 rows x 9 float4-chunks (cols 0..35) = 297 chunks.
    int      goff[5];
    int      vbytes[5];
    uint32_t soff[5];
#pragma unroll
    for (int k = 0; k < 5; ++k) {
        const int i = tid + 64 * k;
        const int r = i / 9, cb = i - 9 * r;
        const int gr = ihb + r, gc0 = iwb + cb * 4;
        int v = 0;
        if (i < 297 && gr < 224 && gc0 < 224) v = min(16, (224 - gc0) * 4);
        goff[k]   = v ? (gr * 224 + gc0) : 0;
        vbytes[k] = v;
        soff[k]   = (uint32_t)(r * IN_STRIDE + cb * 4) * 4u;
    }
    const bool has5 = (tid < 41);

    uint32_t sb[2];
    sb[0] = (uint32_t)__cvta_generic_to_shared(&sIn[0][0]);
    sb[1] = (uint32_t)__cvta_generic_to_shared(&sIn[1][0]);

    const float* xb = x + (size_t)n * CIN * 224 * 224;

    // prologue: issue cin 0 into buffer 0
    {
        const float* xc = xb;
#pragma unroll
        for (int k = 0; k < 4; ++k) cp16(sb[0] + soff[k], xc + goff[k], vbytes[k]);
        if (has5) cp16(sb[0] + soff[4], xc + goff[4], vbytes[4]);
        asm volatile("cp.async.commit_group;\n");
    }

    unsigned long long pacc[8][4];   // [filter-pair][x-output]
#pragma unroll
    for (int fp = 0; fp < 8; ++fp)
#pragma unroll
        for (int j = 0; j < 4; ++j) pacc[fp][j] = 0ull;

    const int ty = tid >> 2, txg = tid & 3;

    for (int cin = 0; cin < CIN; ++cin) {
        __syncthreads();   // everyone done with buf[(cin+1)&1] (iter cin-1); also weights staged
        if (cin + 1 < CIN) {
            const float* xc = xb + (size_t)(cin + 1) * 224 * 224;
            const uint32_t b = sb[(cin + 1) & 1];
#pragma unroll
            for (int k = 0; k < 4; ++k) cp16(b + soff[k], xc + goff[k], vbytes[k]);
            if (has5) cp16(b + soff[4], xc + goff[4], vbytes[4]);
            asm volatile("cp.async.commit_group;\n");
            asm volatile("cp.async.wait_group 1;\n");   // cin's group complete
        } else {
            asm volatile("cp.async.wait_group 0;\n");
        }
        __syncthreads();   // cin's buffer visible to all threads

        const float* inb = &sIn[cin & 1][(2 * ty) * IN_STRIDE + 8 * txg];
        const unsigned long long* wq = sW2 + cin * 72;   // + (r*3+col)*8 + fp
#pragma unroll
        for (int r = 0; r < 3; ++r) {
            const float4 v0 = *(const float4*)(inb + r * IN_STRIDE);
            const float4 v1 = *(const float4*)(inb + r * IN_STRIDE + 4);
            const float  v8 = inb[r * IN_STRIDE + 8];
            // broadcast each input into both f32x2 lanes (shared by all 8 pairs)
            unsigned long long bIn[9];
            bIn[0] = pack2(v0.x, v0.x); bIn[1] = pack2(v0.y, v0.y);
            bIn[2] = pack2(v0.z, v0.z); bIn[3] = pack2(v0.w, v0.w);
            bIn[4] = pack2(v1.x, v1.x); bIn[5] = pack2(v1.y, v1.y);
            bIn[6] = pack2(v1.z, v1.z); bIn[7] = pack2(v1.w, v1.w);
            bIn[8] = pack2(v8, v8);
            const unsigned long long* wr = wq + r * 24;
#pragma unroll
            for (int fp = 0; fp < 8; ++fp) {
                const unsigned long long w0 = wr[fp];        // LDS.64, warp-broadcast
                const unsigned long long w1 = wr[8 + fp];
                const unsigned long long w2 = wr[16 + fp];
                ffma2(pacc[fp][0], w0, bIn[0]); ffma2(pacc[fp][0], w1, bIn[1]); ffma2(pacc[fp][0], w2, bIn[2]);
                ffma2(pacc[fp][1], w0, bIn[2]); ffma2(pacc[fp][1], w1, bIn[3]); ffma2(pacc[fp][1], w2, bIn[4]);
                ffma2(pacc[fp][2], w0, bIn[4]); ffma2(pacc[fp][2], w1, bIn[5]); ffma2(pacc[fp][2], w2, bIn[6]);
                ffma2(pacc[fp][3], w0, bIn[6]); ffma2(pacc[fp][3], w1, bIn[7]); ffma2(pacc[fp][3], w2, bIn[8]);
            }
        }
    }

    // unpack, store outputs (+bias) and per-filter partial sums (no bias)
    const int oy = tyT * 16 + ty, oxb = txT * 16 + 4 * txg;
    float acc[16][4];
#pragma unroll
    for (int fp = 0; fp < 8; ++fp)
#pragma unroll
        for (int j = 0; j < 4; ++j)
            unpack2(pacc[fp][j], acc[2 * fp][j], acc[2 * fp + 1][j]);

    float psum[16];
#pragma unroll
    for (int f = 0; f < 16; ++f) {
        const int cf = cfg * 16 + f;
        const float b = bc[cf];
        float4 o = make_float4(acc[f][0] + b, acc[f][1] + b, acc[f][2] + b, acc[f][3] + b);
        *(float4*)&g_A[((size_t)(n * CF + cf) * HFD + oy) * WFD + oxb] = o;
        psum[f] = acc[f][0] + acc[f][1] + acc[f][2] + acc[f][3];
    }
#pragma unroll
    for (int f = 0; f < 16; ++f)
#pragma unroll
        for (int o = 16; o; o >>= 1)
            psum[f] += __shfl_xor_sync(0xffffffffu, psum[f], o);
    const int wid = tid >> 5, lid = tid & 31;
    if (lid == 0) {
#pragma unroll
        for (int f = 0; f < 16; ++f) sred[wid][f] = psum[f];
    }
    __syncthreads();
    if (tid < 16)
        g_Spart[(size_t)(n * CF + cfg * 16 + tid) * 49 + blockIdx.x] =
            sred[0][tid] + sred[1][tid];
}

// ============================================================
// 2) reduce partial sums: S[n,cf] = sum_tiles + 12544*bc[cf]
// ============================================================
__global__ void gap_kernel(const float* __restrict__ bc) {
    const int idx = blockIdx.x * 256 + threadIdx.x;
    if (idx >= NB * CF) return;
    const float* p = g_Spart + (size_t)idx * 49;
    float s = 0.f;
#pragma unroll
    for (int i = 0; i < 49; ++i) s += p[i];
    g_S[idx] = s + 12544.f * bc[idx % CF];
}

// ============================================================
// 3) logits[n,c] = mean(A) . Wf[c,:] + bf[c]  -> d_out[0:16000]
// ============================================================
__global__ void logits_kernel(const float* __restrict__ Wf, const float* __restrict__ bf,
                              float* __restrict__ out) {
    const int idx = blockIdx.x * 256 + threadIdx.x;
    if (idx >= NB * NC) return;
    const int n = idx / NC, c = idx % NC;
    const float inv = 1.f / 12544.f;
    float s = bf[c];
    const float* sp = g_S + n * CF;
    const float* wp = Wf + (size_t)c * CF;
#pragma unroll 4
    for (int ch = 0; ch < CF; ++ch) s += (sp[ch] * inv) * wp[ch];
    out[idx] = s;
}

// ============================================================
// 4) top-2 per sample, parallel + tree merge.
//    Tie-break: lower index wins (matches lax.top_k).
// ============================================================
__global__ void topk_kernel(const float* __restrict__ logits) {
    const int n = blockIdx.x, tid = threadIdx.x;   // block 256
    const float* lp = logits + n * NC;
    float v1 = -3.4e38f, v2 = -3.4e38f;
    int i1 = NC, i2 = NC;
    for (int c = tid; c < NC; c += 256) {
        const float v = lp[c];     // c ascending => strict > keeps earliest index
        if (v > v1) { v2 = v1; i2 = i1; v1 = v; i1 = c; }
        else if (v > v2) { v2 = v; i2 = c; }
    }
    __shared__ float sv1[256], sv2[256];
    __shared__ int   si1[256], si2[256];
    sv1[tid] = v1; sv2[tid] = v2; si1[tid] = i1; si2[tid] = i2;
    __syncthreads();
    for (int s = 128; s; s >>= 1) {
        if (tid < s) {
            const float a1 = sv1[tid],     a2 = sv2[tid];
            const int   ja1 = si1[tid],    ja2 = si2[tid];
            const float b1 = sv1[tid + s], b2 = sv2[tid + s];
            const int   jb1 = si1[tid + s], jb2 = si2[tid + s];
            float f1, f2; int j1, j2;
            if (b1 > a1 || (b1 == a1 && jb1 < ja1)) {
                f1 = b1; j1 = jb1;
                if (a1 > b2 || (a1 == b2 && ja1 < jb2)) { f2 = a1; j2 = ja1; }
                else                                    { f2 = b2; j2 = jb2; }
            } else {
                f1 = a1; j1 = ja1;
                if (b1 > a2 || (b1 == a2 && jb1 < ja2)) { f2 = b1; j2 = jb1; }
                else                                    { f2 = a2; j2 = ja2; }
            }
            sv1[tid] = f1; sv2[tid] = f2; si1[tid] = j1; si2[tid] = j2;
        }
        __syncthreads();
    }
    if (tid == 0) {
        g_labels[n * 2 + 0] = si1[0];
        g_labels[n * 2 + 1] = si2[0];
    }
}

// ============================================================
// 5) per-(n,k,ch) GradCAM++ channel weights (G spatially constant)
// ============================================================
__global__ void wgt_kernel(const float* __restrict__ Wf) {
    const int nk = blockIdx.x, ch = threadIdx.x;   // grid 32, block 128
    if (ch == 0) { g_mm[nk * 2] = 0x7f800000u; g_mm[nk * 2 + 1] = 0u; }
    const int n = nk >> 1;
    const int l = g_labels[nk];
    const float g  = Wf[(size_t)l * CF + ch] * (1.f / 12544.f);
    const float s  = g_S[n * CF + ch];
    const float g2 = g * g;
    const float denom = 2.f * g2 + g2 * g * s + EPSF;
    const float alpha = g2 / denom;
    g_wgt[nk * CF + ch] = 12544.f * alpha * fmaxf(g, 0.f);
}

// ============================================================
// 6) cam = relu(sum_ch wgt*A), both k per pass; min/max via atomics
// ============================================================
__global__ void cam_kernel() {
    const int n = blockIdx.y;
    const int p = blockIdx.x * 256 + threadIdx.x;   // grid.x=49 -> exactly 12544
    __shared__ float w0s[CF], w1s[CF];
    if (threadIdx.x < CF) {
        w0s[threadIdx.x] = g_wgt[(n * 2 + 0) * CF + threadIdx.x];
        w1s[threadIdx.x] = g_wgt[(n * 2 + 1) * CF + threadIdx.x];
    }
    __syncthreads();
    const float* Ap = g_A + (size_t)n * CF * P_SP + p;
    float a0 = 0.f, a1 = 0.f;
#pragma unroll 4
    for (int ch = 0; ch < CF; ++ch) {
        const float a = Ap[(size_t)ch * P_SP];
        a0 += w0s[ch] * a;
        a1 += w1s[ch] * a;
    }
    const float c0 = fmaxf(a0, 0.f), c1 = fmaxf(a1, 0.f);
    g_cam[(size_t)(n * 2 + 0) * P_SP + p] = c0;
    g_cam[(size_t)(n * 2 + 1) * P_SP + p] = c1;

    float mn0 = c0, mx0 = c0, mn1 = c1, mx1 = c1;
#pragma unroll
    for (int o = 16; o; o >>= 1) {
        mn0 = fminf(mn0, __shfl_xor_sync(0xffffffffu, mn0, o));
        mx0 = fmaxf(mx0, __shfl_xor_sync(0xffffffffu, mx0, o));
        mn1 = fminf(mn1, __shfl_xor_sync(0xffffffffu, mn1, o));
        mx1 = fmaxf(mx1, __shfl_xor_sync(0xffffffffu, mx1, o));
    }
    __shared__ float smn0[8], smx0[8], smn1[8], smx1[8];
    const int w = threadIdx.x >> 5, l = threadIdx.x & 31;
    if (l == 0) { smn0[w] = mn0; smx0[w] = mx0; smn1[w] = mn1; smx1[w] = mx1; }
    __syncthreads();
    if (threadIdx.x == 0) {
        float a = smn0[0], b = smx0[0], c = smn1[0], d = smx1[0];
#pragma unroll
        for (int i = 1; i < 8; ++i) {
            a = fminf(a, smn0[i]); b = fmaxf(b, smx0[i]);
            c = fminf(c, smn1[i]); d = fmaxf(d, smx1[i]);
        }
        atomicMin(&g_mm[(n * 2 + 0) * 2 + 0], __float_as_uint(a));
        atomicMax(&g_mm[(n * 2 + 0) * 2 + 1], __float_as_uint(b));
        atomicMin(&g_mm[(n * 2 + 1) * 2 + 0], __float_as_uint(c));
        atomicMax(&g_mm[(n * 2 + 1) * 2 + 1], __float_as_uint(d));
    }
}

// ============================================================
// 7) normalize + bilinear x2 upsample + threshold + bbox/score
// ============================================================
__global__ void final_kernel(float* __restrict__ out) {
    const int nk = blockIdx.x;                    // grid 32, block 256
    const int tid = threadIdx.x;
    const float mn = __uint_as_float(g_mm[nk * 2 + 0]);
    const float mx = __uint_as_float(g_mm[nk * 2 + 1]);
    const float inv = 1.f / (mx - mn + EPSF);
    const float* cm = g_cam + (size_t)nk * P_SP;

    int minx = 1 << 29, miny = 1 << 29, maxx = -1, maxy = -1, cnt = 0;
    float sum = 0.f;
    for (int p = tid; p < 224 * 224; p += 256) {
        const int dy = p / 224, dx = p % 224;
        float sy = fmaxf(0.5f * (float)dy - 0.25f, 0.f);
        float sx = fmaxf(0.5f * (float)dx - 0.25f, 0.f);
        int iy = (int)sy; float fy = sy - (float)iy; int iy1 = min(iy + 1, 111);
        int ix = (int)sx; float fx = sx - (float)ix; int ix1 = min(ix + 1, 111);
        iy = min(iy, 111); ix = min(ix, 111);
        const float c00 = (cm[iy  * 112 + ix ] - mn) * inv;
        const float c01 = (cm[iy  * 112 + ix1] - mn) * inv;
        const float c10 = (cm[iy1 * 112 + ix ] - mn) * inv;
        const float c11 = (cm[iy1 * 112 + ix1] - mn) * inv;
        const float v = (1.f - fy) * ((1.f - fx) * c00 + fx * c01)
                      +        fy  * ((1.f - fx) * c10 + fx * c11);
        if (v >= 0.35f) {
            ++cnt; sum += v;
            minx = min(minx, dx); maxx = max(maxx, dx);
            miny = min(miny, dy); maxy = max(maxy, dy);
        }
    }

    __shared__ int   ri[256];
    __shared__ float rf[256];
    ri[tid] = minx; __syncthreads();
    for (int s = 128; s; s >>= 1) { if (tid < s) ri[tid] = min(ri[tid], ri[tid + s]); __syncthreads(); }
    minx = ri[0]; __syncthreads();
    ri[tid] = miny; __syncthreads();
    for (int s = 128; s; s >>= 1) { if (tid < s) ri[tid] = min(ri[tid], ri[tid + s]); __syncthreads(); }
    miny = ri[0]; __syncthreads();
    ri[tid] = maxx; __syncthreads();
    for (int s = 128; s; s >>= 1) { if (tid < s) ri[tid] = max(ri[tid], ri[tid + s]); __syncthreads(); }
    maxx = ri[0]; __syncthreads();
    ri[tid] = maxy; __syncthreads();
    for (int s = 128; s; s >>= 1) { if (tid < s) ri[tid] = max(ri[tid], ri[tid + s]); __syncthreads(); }
    maxy = ri[0]; __syncthreads();
    ri[tid] = cnt; __syncthreads();
    for (int s = 128; s; s >>= 1) { if (tid < s) ri[tid] += ri[tid + s]; __syncthreads(); }
    cnt = ri[0]; __syncthreads();
    rf[tid] = sum; __syncthreads();
    for (int s = 128; s; s >>= 1) { if (tid < s) rf[tid] += rf[tid + s]; __syncthreads(); }
    sum = rf[0];

    if (tid == 0) {
        const bool valid = (cnt > 0);
        float* boxes = out + 16000;
        boxes[nk * 4 + 0] = valid ? (float)minx : -1.f;
        boxes[nk * 4 + 1] = valid ? (float)miny : -1.f;
        boxes[nk * 4 + 2] = valid ? (float)maxx : -1.f;
        boxes[nk * 4 + 3] = valid ? (float)maxy : -1.f;
        out[16128 + nk] = (float)g_labels[nk];
        out[16160 + nk] = valid ? sum / (float)cnt : 0.f;
        out[16192 + nk] = valid ? 1.f : 0.f;
    }
}

// ============================================================
extern "C" void kernel_launch(void* const* d_in, const int* in_sizes, int n_in,
                              void* d_out, int out_size) {
    const float* x  = (const float*)d_in[0];
    const float* Wc = (const float*)d_in[1];
    const float* bc = (const float*)d_in[2];
    const float* Wf = (const float*)d_in[3];
    const float* bf = (const float*)d_in[4];
    float* out = (float*)d_out;

    conv_kernel<<<dim3(49, 8, 16), 64>>>(x, Wc, bc);
    gap_kernel<<<8, 256>>>(bc);
    logits_kernel<<<(NB * NC + 255) / 256, 256>>>(Wf, bf, out);
    topk_kernel<<<NB, 256>>>(out);
    wgt_kernel<<<NB * 2, CF>>>(Wf);
    cam_kernel<<<dim3(49, NB), 256>>>();
    final_kernel<<<NB * 2, 256>>>(out);
}